// round 9
// baseline (speedup 1.0000x reference)
#include <cuda_runtime.h>
#include <cuda_fp16.h>

#define C 128
#define NUM_ITERS 10
#define MAXN 500000
#define PGRID 592          // 4 blocks/SM * 148 SMs co-resident
#define PBLK  256
#define STAGES 4
#define CONV_TOL 1e-4f

// Scratch (__device__ globals, no allocation).
__device__ float g_b[C];
__device__ float g_colsum[NUM_ITERS + 1][C];
__device__ int   g_arrive;                       // monotonic arrival counter
__device__ int   g_gen;                          // barrier generation (separate line)
__device__ int   g_tA, g_tB;                     // colsum indices for final pass
__device__ uint4 g_E8[(size_t)MAXN * 8];         // E = exp(S) fp8 e4m3, 128 B/row

// ---- fp8 helpers ------------------------------------------------------------
__device__ __forceinline__ unsigned short pack_fp8x2(float hi, float lo) {
    unsigned short v;
    asm("cvt.rn.satfinite.e4m3x2.f32 %0, %1, %2;" : "=h"(v) : "f"(hi), "f"(lo));
    return v;
}
__device__ __forceinline__ __half2 fp8x2_to_h2(unsigned short p) {
    unsigned r;
    asm("cvt.rn.f16x2.e4m3x2 %0, %1;" : "=r"(r) : "h"(p));
    return *reinterpret_cast<__half2*>(&r);
}

// ---- cache-policy helpers ---------------------------------------------------
__device__ __forceinline__ unsigned long long pol_evict_last() {
    unsigned long long p;
    asm("createpolicy.fractional.L2::evict_last.b64 %0, 1.0;" : "=l"(p));
    return p;
}
__device__ __forceinline__ unsigned long long pol_evict_first() {
    unsigned long long p;
    asm("createpolicy.fractional.L2::evict_first.b64 %0, 1.0;" : "=l"(p));
    return p;
}
__device__ __forceinline__ float4 ldg_hint_f4(const float4* p, unsigned long long pol) {
    float4 q;
    asm volatile("ld.global.nc.L2::cache_hint.v4.f32 {%0,%1,%2,%3}, [%4], %5;"
                 : "=f"(q.x), "=f"(q.y), "=f"(q.z), "=f"(q.w) : "l"(p), "l"(pol));
    return q;
}
__device__ __forceinline__ void stg_hint_u32(unsigned* p, unsigned v, unsigned long long pol) {
    asm volatile("st.global.L2::cache_hint.u32 [%0], %1, %2;"
                 :: "l"(p), "r"(v), "l"(pol) : "memory");
}

// ---- 256-bit global access (v8.b32 — the width evict modifiers require) -----
__device__ __forceinline__ void ldg_v8_ef(float* f, const float* p) {
    unsigned r0, r1, r2, r3, r4, r5, r6, r7;
    asm volatile("ld.global.nc.L2::evict_first.v8.b32 {%0,%1,%2,%3,%4,%5,%6,%7}, [%8];"
                 : "=r"(r0), "=r"(r1), "=r"(r2), "=r"(r3),
                   "=r"(r4), "=r"(r5), "=r"(r6), "=r"(r7) : "l"(p));
    f[0] = __uint_as_float(r0); f[1] = __uint_as_float(r1);
    f[2] = __uint_as_float(r2); f[3] = __uint_as_float(r3);
    f[4] = __uint_as_float(r4); f[5] = __uint_as_float(r5);
    f[6] = __uint_as_float(r6); f[7] = __uint_as_float(r7);
}
__device__ __forceinline__ void stg_v8_ef(float* p, const float* f) {
    asm volatile("st.global.L2::evict_first.v8.b32 [%0], {%1,%2,%3,%4,%5,%6,%7,%8};"
                 :: "l"(p),
                    "r"(__float_as_uint(f[0])), "r"(__float_as_uint(f[1])),
                    "r"(__float_as_uint(f[2])), "r"(__float_as_uint(f[3])),
                    "r"(__float_as_uint(f[4])), "r"(__float_as_uint(f[5])),
                    "r"(__float_as_uint(f[6])), "r"(__float_as_uint(f[7]))
                 : "memory");
}

// ---- cp.async helpers -------------------------------------------------------
__device__ __forceinline__ void cp_async16(unsigned dst, const void* src) {
    asm volatile("cp.async.cg.shared.global [%0], [%1], 16;" :: "r"(dst), "l"(src) : "memory");
}
#define CP_COMMIT() asm volatile("cp.async.commit_group;" ::: "memory")
#define CP_WAIT(n)  asm volatile("cp.async.wait_group %0;" :: "n"(n) : "memory")
__device__ __forceinline__ uint4 lds128(unsigned addr) {
    uint4 q;
    asm volatile("ld.shared.v4.u32 {%0,%1,%2,%3}, [%4];"
                 : "=r"(q.x), "=r"(q.y), "=r"(q.z), "=r"(q.w) : "r"(addr));
    return q;
}

// ---------------------------------------------------------------------------
__global__ void init_k(const float* __restrict__ ratios,
                       const int* __restrict__ total_num) {
    int j = threadIdx.x;
    float tn = (float)(*total_num);
    g_b[j] = ratios[j] * tn;
    #pragma unroll
    for (int t = 0; t <= NUM_ITERS; ++t) g_colsum[t][j] = 0.0f;
    if (j == 0) {
        g_arrive = 0; g_gen = 1;
        g_tA = NUM_ITERS - 1; g_tB = NUM_ITERS;
    }
}

// ---------------------------------------------------------------------------
// Pass 1 (iteration 1, v0=1) fused with E = exp(S) -> fp8 store. Unroll x4.
// ---------------------------------------------------------------------------
__global__ void __launch_bounds__(256)
pass1_k(const float4* __restrict__ S4, int N) {
    const int lane = threadIdx.x & 31;
    const int gwarp = blockIdx.x * (blockDim.x >> 5) + (threadIdx.x >> 5);
    const int nwarps = gridDim.x * (blockDim.x >> 5);
    const unsigned long long pol_ef = pol_evict_first();
    const unsigned long long pol_el = pol_evict_last();

    float c0 = 0.f, c1 = 0.f, c2 = 0.f, c3 = 0.f;
    unsigned* __restrict__ E8 = reinterpret_cast<unsigned*>(g_E8);

    int row = gwarp;
    for (; row + 3 * nwarps < N; row += 4 * nwarps) {
        float4 s[4];
        #pragma unroll
        for (int m = 0; m < 4; ++m)
            s[m] = ldg_hint_f4(&S4[(size_t)(row + m * nwarps) * 32 + lane], pol_ef);

        float e[4][4], p[4];
        #pragma unroll
        for (int m = 0; m < 4; ++m) {
            e[m][0] = __expf(s[m].x); e[m][1] = __expf(s[m].y);
            e[m][2] = __expf(s[m].z); e[m][3] = __expf(s[m].w);
            unsigned pk = (unsigned)pack_fp8x2(e[m][1], e[m][0])
                        | ((unsigned)pack_fp8x2(e[m][3], e[m][2]) << 16);
            stg_hint_u32(&E8[(size_t)(row + m * nwarps) * 32 + lane], pk, pol_el);
            p[m] = (e[m][0] + e[m][1]) + (e[m][2] + e[m][3]);
        }
        #pragma unroll
        for (int o = 16; o; o >>= 1) {
            #pragma unroll
            for (int m = 0; m < 4; ++m)
                p[m] += __shfl_xor_sync(0xffffffffu, p[m], o);
        }
        #pragma unroll
        for (int m = 0; m < 4; ++m) {
            float u = 1.0f / p[m];
            c0 = fmaf(u, e[m][0], c0); c1 = fmaf(u, e[m][1], c1);
            c2 = fmaf(u, e[m][2], c2); c3 = fmaf(u, e[m][3], c3);
        }
    }
    for (; row < N; row += nwarps) {
        float4 s = ldg_hint_f4(&S4[(size_t)row * 32 + lane], pol_ef);
        float e0 = __expf(s.x), e1 = __expf(s.y), e2 = __expf(s.z), e3 = __expf(s.w);
        unsigned pk = (unsigned)pack_fp8x2(e1, e0) | ((unsigned)pack_fp8x2(e3, e2) << 16);
        stg_hint_u32(&E8[(size_t)row * 32 + lane], pk, pol_el);
        float p = (e0 + e1) + (e2 + e3);
        #pragma unroll
        for (int o = 16; o; o >>= 1) p += __shfl_xor_sync(0xffffffffu, p, o);
        float u = 1.0f / p;
        c0 = fmaf(u, e0, c0); c1 = fmaf(u, e1, c1);
        c2 = fmaf(u, e2, c2); c3 = fmaf(u, e3, c3);
    }

    __shared__ float scol[C];
    if (threadIdx.x < C) scol[threadIdx.x] = 0.0f;
    __syncthreads();
    int col = lane * 4;
    atomicAdd(&scol[col + 0], c0);
    atomicAdd(&scol[col + 1], c1);
    atomicAdd(&scol[col + 2], c2);
    atomicAdd(&scol[col + 3], c3);
    __syncthreads();
    if (threadIdx.x < C)
        atomicAdd(&g_colsum[1][threadIdx.x], scol[threadIdx.x]);
}

// ---------------------------------------------------------------------------
// Persistent kernel: iterations 2..10, cp.async pipeline, decoupled-spin
// grid barrier, deterministic convergence early-exit.
// ---------------------------------------------------------------------------
__global__ void __launch_bounds__(PBLK, 4)
sinkiters_k(int N) {
    const int lane = threadIdx.x & 31;
    const int sub = lane & 7;
    const int wid = threadIdx.x >> 5;
    const int gwarp = blockIdx.x * (PBLK >> 5) + wid;
    const int nwarps = PGRID * (PBLK >> 5);
    const int G = N >> 2;                  // groups of 4 rows (512 B)
    const int rem = N & 3;

    __shared__ float sv[C];
    __shared__ float scol[C];
    __shared__ __align__(16) unsigned char pipe[PBLK / 32][STAGES * 512];

    const unsigned sbuf =
        (unsigned)__cvta_generic_to_shared(&pipe[wid][0]) + (unsigned)lane * 16;
    const int total = (gwarp < G) ? ((G - gwarp - 1) / nwarps + 1) : 0;

    for (int t = 2; t <= NUM_ITERS; ++t) {
        int bigflag = 0;
        if (threadIdx.x < C) {
            float vn = g_b[threadIdx.x] / __ldcg(&g_colsum[t - 1][threadIdx.x]);
            sv[threadIdx.x] = vn;
            scol[threadIdx.x] = 0.0f;
            if (t >= 3) {
                float vo = g_b[threadIdx.x] / __ldcg(&g_colsum[t - 2][threadIdx.x]);
                bigflag = fabsf(vn - vo) > CONV_TOL * vn;
            }
        }
        int moving = __syncthreads_or(bigflag);
        if (t >= 3 && !moving) {
            if (blockIdx.x == 0 && threadIdx.x == 0) {
                g_tA = t - 1; g_tB = t - 1;
                __threadfence();
            }
            break;                          // all blocks break together
        }

        __half2 v2[8], c2[8];
        #pragma unroll
        for (int k = 0; k < 8; ++k) {
            v2[k] = __floats2half2_rn(sv[sub * 16 + 2 * k], sv[sub * 16 + 2 * k + 1]);
            c2[k] = __floats2half2_rn(0.f, 0.f);
        }

        auto process = [&](uint4 q) {
            __half2 h[8];
            h[0] = fp8x2_to_h2((unsigned short)(q.x & 0xffff));
            h[1] = fp8x2_to_h2((unsigned short)(q.x >> 16));
            h[2] = fp8x2_to_h2((unsigned short)(q.y & 0xffff));
            h[3] = fp8x2_to_h2((unsigned short)(q.y >> 16));
            h[4] = fp8x2_to_h2((unsigned short)(q.z & 0xffff));
            h[5] = fp8x2_to_h2((unsigned short)(q.z >> 16));
            h[6] = fp8x2_to_h2((unsigned short)(q.w & 0xffff));
            h[7] = fp8x2_to_h2((unsigned short)(q.w >> 16));
            __half2 pa = __hmul2(h[0], v2[0]);
            __half2 pb = __hmul2(h[4], v2[4]);
            pa = __hfma2(h[1], v2[1], pa);
            pb = __hfma2(h[5], v2[5], pb);
            pa = __hfma2(h[2], v2[2], pa);
            pb = __hfma2(h[6], v2[6], pb);
            pa = __hfma2(h[3], v2[3], pa);
            pb = __hfma2(h[7], v2[7], pb);
            pa = __hadd2(pa, pb);
            float2 pf = __half22float2(pa);
            float p = pf.x + pf.y;
            p += __shfl_xor_sync(0xffffffffu, p, 4);
            p += __shfl_xor_sync(0xffffffffu, p, 2);
            p += __shfl_xor_sync(0xffffffffu, p, 1);
            __half2 u2 = __float2half2_rn(1.0f / p);
            #pragma unroll
            for (int k = 0; k < 8; ++k)
                c2[k] = __hfma2(u2, h[k], c2[k]);
        };

        int j = 0;
        #pragma unroll
        for (int s = 0; s < STAGES; ++s) {
            if (j < total)
                cp_async16(sbuf + s * 512,
                           &g_E8[(size_t)(gwarp + (size_t)j * nwarps) * 32 + lane]);
            CP_COMMIT();
            ++j;
        }
        for (int k = 0; k < total; ++k) {
            CP_WAIT(STAGES - 1);
            uint4 q = lds128(sbuf + (k & (STAGES - 1)) * 512);
            process(q);
            if (j < total)
                cp_async16(sbuf + (j & (STAGES - 1)) * 512,
                           &g_E8[(size_t)(gwarp + (size_t)j * nwarps) * 32 + lane]);
            CP_COMMIT();
            ++j;
        }
        CP_WAIT(0);

        if (gwarp < rem && lane < 8) {   // remainder rows (N % 4)
            int row = G * 4 + gwarp;
            uint4 q = g_E8[(size_t)row * 8 + sub];
            __half2 h[8];
            h[0] = fp8x2_to_h2((unsigned short)(q.x & 0xffff));
            h[1] = fp8x2_to_h2((unsigned short)(q.x >> 16));
            h[2] = fp8x2_to_h2((unsigned short)(q.y & 0xffff));
            h[3] = fp8x2_to_h2((unsigned short)(q.y >> 16));
            h[4] = fp8x2_to_h2((unsigned short)(q.z & 0xffff));
            h[5] = fp8x2_to_h2((unsigned short)(q.z >> 16));
            h[6] = fp8x2_to_h2((unsigned short)(q.w & 0xffff));
            h[7] = fp8x2_to_h2((unsigned short)(q.w >> 16));
            float p = 0.f;
            #pragma unroll
            for (int k = 0; k < 8; ++k) {
                float2 pr = __half22float2(__hmul2(h[k], v2[k]));
                p += pr.x + pr.y;
            }
            p += __shfl_xor_sync(0x000000ffu, p, 4);
            p += __shfl_xor_sync(0x000000ffu, p, 2);
            p += __shfl_xor_sync(0x000000ffu, p, 1);
            __half2 u2 = __float2half2_rn(1.0f / p);
            #pragma unroll
            for (int k = 0; k < 8; ++k)
                c2[k] = __hfma2(u2, h[k], c2[k]);
        }

        #pragma unroll
        for (int k = 0; k < 8; ++k) {
            unsigned pk = *reinterpret_cast<unsigned*>(&c2[k]);
            unsigned o1 = __shfl_xor_sync(0xffffffffu, pk, 8);
            __half2 s = __hadd2(c2[k], *reinterpret_cast<__half2*>(&o1));
            unsigned ps = *reinterpret_cast<unsigned*>(&s);
            unsigned o2 = __shfl_xor_sync(0xffffffffu, ps, 16);
            c2[k] = __hadd2(s, *reinterpret_cast<__half2*>(&o2));
        }
        if (lane < 8) {
            #pragma unroll
            for (int k = 0; k < 8; ++k) {
                float2 cf = __half22float2(c2[k]);
                atomicAdd(&scol[sub * 16 + 2 * k], cf.x);
                atomicAdd(&scol[sub * 16 + 2 * k + 1], cf.y);
            }
        }
        __syncthreads();
        if (threadIdx.x < C)
            atomicAdd(&g_colsum[t][threadIdx.x], scol[threadIdx.x]);

        // Decoupled grid barrier: arrive on g_arrive, spin on g_gen only.
        if (t < NUM_ITERS) {
            __threadfence();
            __syncthreads();
            if (threadIdx.x == 0) {
                int prev = atomicAdd(&g_arrive, 1);
                const int target = (t - 1) * PGRID;
                if (prev == target - 1) {
                    atomicExch(&g_gen, t);      // release the generation
                } else {
                    int cur;
                    do {
                        asm volatile("ld.global.cg.s32 %0, [%1];" : "=r"(cur) : "l"(&g_gen));
                        if (cur < t) __nanosleep(32);
                    } while (cur < t);
                }
                __threadfence();
            }
            __syncthreads();
        }
    }
}

// ---------------------------------------------------------------------------
// Final: P_ij = u_i * exp(S_ij) * v_tB[j], u_i = 1/sum_j exp(S_ij)*v_tA[j].
// 16 lanes/row, 256-bit loads/stores, 2 rows per warp per v8, unroll x4.
// ---------------------------------------------------------------------------
__global__ void __launch_bounds__(256)
final_k(const float* __restrict__ S, float* __restrict__ out, int N) {
    const int lane = threadIdx.x & 31;
    const int sub = lane & 15;
    const int half = lane >> 4;
    const int gwarp = blockIdx.x * (blockDim.x >> 5) + (threadIdx.x >> 5);
    const int nwarps = gridDim.x * (blockDim.x >> 5);

    __shared__ float sv9[C], sv10[C];
    if (threadIdx.x < C) {
        int tA = __ldcg(&g_tA), tB = __ldcg(&g_tB);
        sv9[threadIdx.x]  = g_b[threadIdx.x] / __ldcg(&g_colsum[tA][threadIdx.x]);
        sv10[threadIdx.x] = g_b[threadIdx.x] / __ldcg(&g_colsum[tB][threadIdx.x]);
    }
    __syncthreads();

    float va[8], vb[8];
    #pragma unroll
    for (int k = 0; k < 8; ++k) {
        va[k] = sv9[sub * 8 + k];
        vb[k] = sv10[sub * 8 + k];
    }

    const int RP = N >> 1;    // row pairs; warp covers rows 2*rp+half
    int rp = gwarp;
    for (; rp + 3 * nwarps < RP; rp += 4 * nwarps) {
        float f[4][8];
        #pragma unroll
        for (int m = 0; m < 4; ++m)
            ldg_v8_ef(f[m], S + ((size_t)(rp + m * nwarps) * 2 + half) * C + sub * 8);

        #pragma unroll
        for (int m = 0; m < 4; ++m) {
            float e[8];
            #pragma unroll
            for (int k = 0; k < 8; ++k) e[k] = __expf(f[m][k]);
            float p0 = fmaf(e[0], va[0], e[1] * va[1]);
            float p1 = fmaf(e[2], va[2], e[3] * va[3]);
            float p2 = fmaf(e[4], va[4], e[5] * va[5]);
            float p3 = fmaf(e[6], va[6], e[7] * va[7]);
            float p = (p0 + p1) + (p2 + p3);
            p += __shfl_xor_sync(0xffffffffu, p, 8);   // 16-lane reduce:
            p += __shfl_xor_sync(0xffffffffu, p, 4);   // stays within half
            p += __shfl_xor_sync(0xffffffffu, p, 2);
            p += __shfl_xor_sync(0xffffffffu, p, 1);
            float u = 1.0f / p;
            float o[8];
            #pragma unroll
            for (int k = 0; k < 8; ++k) o[k] = u * e[k] * vb[k];
            stg_v8_ef(out + ((size_t)(rp + m * nwarps) * 2 + half) * C + sub * 8, o);
        }
    }
    for (; rp < RP; rp += nwarps) {
        float f[8], e[8], o[8];
        ldg_v8_ef(f, S + ((size_t)rp * 2 + half) * C + sub * 8);
        #pragma unroll
        for (int k = 0; k < 8; ++k) e[k] = __expf(f[k]);
        float p0 = fmaf(e[0], va[0], e[1] * va[1]);
        float p1 = fmaf(e[2], va[2], e[3] * va[3]);
        float p2 = fmaf(e[4], va[4], e[5] * va[5]);
        float p3 = fmaf(e[6], va[6], e[7] * va[7]);
        float p = (p0 + p1) + (p2 + p3);
        p += __shfl_xor_sync(0xffffffffu, p, 8);
        p += __shfl_xor_sync(0xffffffffu, p, 4);
        p += __shfl_xor_sync(0xffffffffu, p, 2);
        p += __shfl_xor_sync(0xffffffffu, p, 1);
        float u = 1.0f / p;
        #pragma unroll
        for (int k = 0; k < 8; ++k) o[k] = u * e[k] * vb[k];
        stg_v8_ef(out + ((size_t)rp * 2 + half) * C + sub * 8, o);
    }
    // Odd-N remainder row (N even for this dataset; generic safety).
    if ((N & 1) && gwarp == 0 && half == 0) {
        int row = N - 1;
        float f[8], e[8], o[8];
        ldg_v8_ef(f, S + (size_t)row * C + sub * 8);
        #pragma unroll
        for (int k = 0; k < 8; ++k) e[k] = __expf(f[k]);
        float p0 = fmaf(e[0], va[0], e[1] * va[1]);
        float p1 = fmaf(e[2], va[2], e[3] * va[3]);
        float p2 = fmaf(e[4], va[4], e[5] * va[5]);
        float p3 = fmaf(e[6], va[6], e[7] * va[7]);
        float p = (p0 + p1) + (p2 + p3);
        p += __shfl_xor_sync(0x0000ffffu, p, 8);
        p += __shfl_xor_sync(0x0000ffffu, p, 4);
        p += __shfl_xor_sync(0x0000ffffu, p, 2);
        p += __shfl_xor_sync(0x0000ffffu, p, 1);
        float u = 1.0f / p;
        #pragma unroll
        for (int k = 0; k < 8; ++k) o[k] = u * e[k] * vb[k];
        stg_v8_ef(out + (size_t)row * C + sub * 8, o);
    }
}

// ---------------------------------------------------------------------------
extern "C" void kernel_launch(void* const* d_in, const int* in_sizes, int n_in,
                              void* d_out, int out_size) {
    const float* S        = (const float*)d_in[2];
    const float* ratios   = (const float*)d_in[3];
    const int*   totalnum = (const int*)d_in[5];
    const int N = in_sizes[2] / C;

    init_k<<<1, C>>>(ratios, totalnum);
    pass1_k<<<1184, 256>>>((const float4*)S, N);      // iteration 1 + E8 store
    sinkiters_k<<<PGRID, PBLK>>>(N);                  // iterations 2..10 (persistent)
    final_k<<<1184, 256>>>(S, (float*)d_out, N);
}

// round 10
// speedup vs baseline: 1.0459x; 1.0459x over previous
#include <cuda_runtime.h>
#include <cuda_fp16.h>

#define C 128
#define NUM_ITERS 10
#define MAXN 500000
#define PGRID 592          // 4 blocks/SM * 148 SMs co-resident
#define PBLK  256
#define NWARPS_BLK (PBLK / 32)
#define STAGES 4
#define CONV_TOL 1e-4f

// Scratch (__device__ globals, no allocation).
__device__ float g_b[C];
__device__ float g_colsum[NUM_ITERS + 1][C];
__device__ int   g_arrive;                       // monotonic arrival counter
__device__ int   g_gen;                          // barrier generation word
__device__ uint4 g_E8[(size_t)MAXN * 8];         // E = exp(S) fp8 e4m3, 128 B/row

// ---- fp8 helpers ------------------------------------------------------------
__device__ __forceinline__ unsigned short pack_fp8x2(float hi, float lo) {
    unsigned short v;
    asm("cvt.rn.satfinite.e4m3x2.f32 %0, %1, %2;" : "=h"(v) : "f"(hi), "f"(lo));
    return v;
}
__device__ __forceinline__ __half2 fp8x2_to_h2(unsigned short p) {
    unsigned r;
    asm("cvt.rn.f16x2.e4m3x2 %0, %1;" : "=r"(r) : "h"(p));
    return *reinterpret_cast<__half2*>(&r);
}

// ---- cache-policy helpers ---------------------------------------------------
__device__ __forceinline__ unsigned long long pol_evict_last() {
    unsigned long long p;
    asm("createpolicy.fractional.L2::evict_last.b64 %0, 1.0;" : "=l"(p));
    return p;
}
__device__ __forceinline__ unsigned long long pol_evict_first() {
    unsigned long long p;
    asm("createpolicy.fractional.L2::evict_first.b64 %0, 1.0;" : "=l"(p));
    return p;
}
__device__ __forceinline__ void stg_hint_u32(unsigned* p, unsigned v, unsigned long long pol) {
    asm volatile("st.global.L2::cache_hint.u32 [%0], %1, %2;"
                 :: "l"(p), "r"(v), "l"(pol) : "memory");
}
__device__ __forceinline__ void stg_hint_f4(float4* p, float4 v, unsigned long long pol) {
    asm volatile("st.global.L2::cache_hint.v4.f32 [%0], {%1,%2,%3,%4}, %5;"
                 :: "l"(p), "f"(v.x), "f"(v.y), "f"(v.z), "f"(v.w), "l"(pol) : "memory");
}

// ---- cp.async helpers -------------------------------------------------------
__device__ __forceinline__ void cp_async16(unsigned dst, const void* src) {
    asm volatile("cp.async.cg.shared.global [%0], [%1], 16;" :: "r"(dst), "l"(src) : "memory");
}
#define CP_COMMIT() asm volatile("cp.async.commit_group;" ::: "memory")
#define CP_WAIT(n)  asm volatile("cp.async.wait_group %0;" :: "n"(n) : "memory")
__device__ __forceinline__ uint4 lds128(unsigned addr) {
    uint4 q;
    asm volatile("ld.shared.v4.u32 {%0,%1,%2,%3}, [%4];"
                 : "=r"(q.x), "=r"(q.y), "=r"(q.z), "=r"(q.w) : "r"(addr));
    return q;
}

// ---------------------------------------------------------------------------
__global__ void init_k(const float* __restrict__ ratios,
                       const int* __restrict__ total_num) {
    int j = threadIdx.x;
    float tn = (float)(*total_num);
    g_b[j] = ratios[j] * tn;
    #pragma unroll
    for (int t = 0; t <= NUM_ITERS; ++t) g_colsum[t][j] = 0.0f;
    if (j == 0) { g_arrive = 0; g_gen = 0; }
}

// ---------------------------------------------------------------------------
// Grid barrier: arrive on g_arrive, spin on the separate generation word.
// All blocks call with the same monotonically increasing gen sequence.
// ---------------------------------------------------------------------------
__device__ __forceinline__ void grid_barrier(int gen) {
    __threadfence();
    __syncthreads();
    if (threadIdx.x == 0) {
        int prev = atomicAdd(&g_arrive, 1);
        if (prev == gen * PGRID - 1) {
            atomicExch(&g_gen, gen);
        } else {
            int cur;
            do {
                asm volatile("ld.global.cg.s32 %0, [%1];" : "=r"(cur) : "l"(&g_gen));
                if (cur < gen) __nanosleep(32);
            } while (cur < gen);
        }
        __threadfence();
    }
    __syncthreads();
}

// ---------------------------------------------------------------------------
// Grand persistent kernel: pass1 + iterations 2..10 + final, all phases
// fed by per-warp 4-stage cp.async pipelines; grid barriers between phases.
// ---------------------------------------------------------------------------
__global__ void __launch_bounds__(PBLK, 4)
grand_k(const float* __restrict__ S, float* __restrict__ out, int N) {
    const int lane = threadIdx.x & 31;
    const int sub = lane & 7;
    const int wid = threadIdx.x >> 5;
    const int gwarp = blockIdx.x * NWARPS_BLK + wid;
    const int nwarps = PGRID * NWARPS_BLK;
    const unsigned long long pol_el = pol_evict_last();
    const unsigned long long pol_ef = pol_evict_first();

    __shared__ float sv[C];
    __shared__ float svB[C];
    __shared__ float scol[C];
    __shared__ __align__(16) unsigned char pipe[NWARPS_BLK][STAGES * 512];

    const unsigned sbuf =
        (unsigned)__cvta_generic_to_shared(&pipe[wid][0]) + (unsigned)lane * 16;
    const int nrows = (gwarp < N) ? ((N - gwarp - 1) / nwarps + 1) : 0;

    // ======================= Phase A: iteration 1 + E8 store ================
    {
        if (threadIdx.x < C) scol[threadIdx.x] = 0.0f;
        __syncthreads();

        float c0 = 0.f, c1 = 0.f, c2 = 0.f, c3 = 0.f;
        unsigned* __restrict__ E8 = reinterpret_cast<unsigned*>(g_E8);

        int j = 0;
        #pragma unroll
        for (int s = 0; s < STAGES; ++s) {
            if (j < nrows)
                cp_async16(sbuf + s * 512,
                           S + ((size_t)gwarp + (size_t)j * nwarps) * C + lane * 4);
            CP_COMMIT();
            ++j;
        }
        for (int k = 0; k < nrows; ++k) {
            CP_WAIT(STAGES - 1);
            uint4 q = lds128(sbuf + (k & (STAGES - 1)) * 512);
            size_t row = (size_t)gwarp + (size_t)k * nwarps;
            float e0 = __expf(__uint_as_float(q.x));
            float e1 = __expf(__uint_as_float(q.y));
            float e2 = __expf(__uint_as_float(q.z));
            float e3 = __expf(__uint_as_float(q.w));
            unsigned pk = (unsigned)pack_fp8x2(e1, e0)
                        | ((unsigned)pack_fp8x2(e3, e2) << 16);
            stg_hint_u32(&E8[row * 32 + lane], pk, pol_el);
            float p = (e0 + e1) + (e2 + e3);
            #pragma unroll
            for (int o = 16; o; o >>= 1) p += __shfl_xor_sync(0xffffffffu, p, o);
            float u = 1.0f / p;
            c0 = fmaf(u, e0, c0); c1 = fmaf(u, e1, c1);
            c2 = fmaf(u, e2, c2); c3 = fmaf(u, e3, c3);
            if (j < nrows)
                cp_async16(sbuf + (j & (STAGES - 1)) * 512,
                           S + ((size_t)gwarp + (size_t)j * nwarps) * C + lane * 4);
            CP_COMMIT();
            ++j;
        }
        CP_WAIT(0);

        int col = lane * 4;
        atomicAdd(&scol[col + 0], c0);
        atomicAdd(&scol[col + 1], c1);
        atomicAdd(&scol[col + 2], c2);
        atomicAdd(&scol[col + 3], c3);
        __syncthreads();
        if (threadIdx.x < C)
            atomicAdd(&g_colsum[1][threadIdx.x], scol[threadIdx.x]);
    }
    grid_barrier(1);

    // ======================= Phase B: iterations 2..10 ======================
    int tA = NUM_ITERS - 1, tB = NUM_ITERS;
    {
        const int G = N >> 2;
        const int rem = N & 3;
        const int ngrp = (gwarp < G) ? ((G - gwarp - 1) / nwarps + 1) : 0;

        for (int t = 2; t <= NUM_ITERS; ++t) {
            int bigflag = 0;
            if (threadIdx.x < C) {
                float vn = g_b[threadIdx.x] / __ldcg(&g_colsum[t - 1][threadIdx.x]);
                sv[threadIdx.x] = vn;
                scol[threadIdx.x] = 0.0f;
                if (t >= 3) {
                    float vo = g_b[threadIdx.x] / __ldcg(&g_colsum[t - 2][threadIdx.x]);
                    bigflag = fabsf(vn - vo) > CONV_TOL * vn;
                }
            }
            int moving = __syncthreads_or(bigflag);
            if (t >= 3 && !moving) {      // identical decision in every block
                tA = t - 1; tB = t - 1;
                break;
            }

            __half2 v2[8], c2[8];
            #pragma unroll
            for (int k = 0; k < 8; ++k) {
                v2[k] = __floats2half2_rn(sv[sub * 16 + 2 * k], sv[sub * 16 + 2 * k + 1]);
                c2[k] = __floats2half2_rn(0.f, 0.f);
            }

            auto process = [&](uint4 q) {
                __half2 h[8];
                h[0] = fp8x2_to_h2((unsigned short)(q.x & 0xffff));
                h[1] = fp8x2_to_h2((unsigned short)(q.x >> 16));
                h[2] = fp8x2_to_h2((unsigned short)(q.y & 0xffff));
                h[3] = fp8x2_to_h2((unsigned short)(q.y >> 16));
                h[4] = fp8x2_to_h2((unsigned short)(q.z & 0xffff));
                h[5] = fp8x2_to_h2((unsigned short)(q.z >> 16));
                h[6] = fp8x2_to_h2((unsigned short)(q.w & 0xffff));
                h[7] = fp8x2_to_h2((unsigned short)(q.w >> 16));
                __half2 pa = __hmul2(h[0], v2[0]);
                __half2 pb = __hmul2(h[4], v2[4]);
                pa = __hfma2(h[1], v2[1], pa);
                pb = __hfma2(h[5], v2[5], pb);
                pa = __hfma2(h[2], v2[2], pa);
                pb = __hfma2(h[6], v2[6], pb);
                pa = __hfma2(h[3], v2[3], pa);
                pb = __hfma2(h[7], v2[7], pb);
                pa = __hadd2(pa, pb);
                float2 pf = __half22float2(pa);
                float p = pf.x + pf.y;
                p += __shfl_xor_sync(0xffffffffu, p, 4);
                p += __shfl_xor_sync(0xffffffffu, p, 2);
                p += __shfl_xor_sync(0xffffffffu, p, 1);
                __half2 u2 = __float2half2_rn(1.0f / p);
                #pragma unroll
                for (int k = 0; k < 8; ++k)
                    c2[k] = __hfma2(u2, h[k], c2[k]);
            };

            int j = 0;
            #pragma unroll
            for (int s = 0; s < STAGES; ++s) {
                if (j < ngrp)
                    cp_async16(sbuf + s * 512,
                               &g_E8[((size_t)gwarp + (size_t)j * nwarps) * 32 + lane]);
                CP_COMMIT();
                ++j;
            }
            for (int k = 0; k < ngrp; ++k) {
                CP_WAIT(STAGES - 1);
                uint4 q = lds128(sbuf + (k & (STAGES - 1)) * 512);
                process(q);
                if (j < ngrp)
                    cp_async16(sbuf + (j & (STAGES - 1)) * 512,
                               &g_E8[((size_t)gwarp + (size_t)j * nwarps) * 32 + lane]);
                CP_COMMIT();
                ++j;
            }
            CP_WAIT(0);

            if (gwarp < rem && lane < 8) {   // remainder rows (N % 4)
                size_t row = (size_t)G * 4 + gwarp;
                uint4 q = g_E8[row * 8 + sub];
                __half2 h[8];
                h[0] = fp8x2_to_h2((unsigned short)(q.x & 0xffff));
                h[1] = fp8x2_to_h2((unsigned short)(q.x >> 16));
                h[2] = fp8x2_to_h2((unsigned short)(q.y & 0xffff));
                h[3] = fp8x2_to_h2((unsigned short)(q.y >> 16));
                h[4] = fp8x2_to_h2((unsigned short)(q.z & 0xffff));
                h[5] = fp8x2_to_h2((unsigned short)(q.z >> 16));
                h[6] = fp8x2_to_h2((unsigned short)(q.w & 0xffff));
                h[7] = fp8x2_to_h2((unsigned short)(q.w >> 16));
                float p = 0.f;
                #pragma unroll
                for (int k = 0; k < 8; ++k) {
                    float2 pr = __half22float2(__hmul2(h[k], v2[k]));
                    p += pr.x + pr.y;
                }
                p += __shfl_xor_sync(0x000000ffu, p, 4);
                p += __shfl_xor_sync(0x000000ffu, p, 2);
                p += __shfl_xor_sync(0x000000ffu, p, 1);
                __half2 u2 = __float2half2_rn(1.0f / p);
                #pragma unroll
                for (int k = 0; k < 8; ++k)
                    c2[k] = __hfma2(u2, h[k], c2[k]);
            }

            #pragma unroll
            for (int k = 0; k < 8; ++k) {
                unsigned pk = *reinterpret_cast<unsigned*>(&c2[k]);
                unsigned o1 = __shfl_xor_sync(0xffffffffu, pk, 8);
                __half2 s = __hadd2(c2[k], *reinterpret_cast<__half2*>(&o1));
                unsigned ps = *reinterpret_cast<unsigned*>(&s);
                unsigned o2 = __shfl_xor_sync(0xffffffffu, ps, 16);
                c2[k] = __hadd2(s, *reinterpret_cast<__half2*>(&o2));
            }
            if (lane < 8) {
                #pragma unroll
                for (int k = 0; k < 8; ++k) {
                    float2 cf = __half22float2(c2[k]);
                    atomicAdd(&scol[sub * 16 + 2 * k], cf.x);
                    atomicAdd(&scol[sub * 16 + 2 * k + 1], cf.y);
                }
            }
            __syncthreads();
            if (threadIdx.x < C)
                atomicAdd(&g_colsum[t][threadIdx.x], scol[threadIdx.x]);

            grid_barrier(t);
        }
    }

    // ======================= Phase C: final output ==========================
    {
        if (threadIdx.x < C) {
            sv[threadIdx.x]  = g_b[threadIdx.x] / __ldcg(&g_colsum[tA][threadIdx.x]);
            svB[threadIdx.x] = g_b[threadIdx.x] / __ldcg(&g_colsum[tB][threadIdx.x]);
        }
        __syncthreads();

        float4 va = reinterpret_cast<const float4*>(sv)[lane];
        float4 vb = reinterpret_cast<const float4*>(svB)[lane];
        float4* __restrict__ out4 = reinterpret_cast<float4*>(out);

        int j = 0;
        #pragma unroll
        for (int s = 0; s < STAGES; ++s) {
            if (j < nrows)
                cp_async16(sbuf + s * 512,
                           S + ((size_t)gwarp + (size_t)j * nwarps) * C + lane * 4);
            CP_COMMIT();
            ++j;
        }
        for (int k = 0; k < nrows; ++k) {
            CP_WAIT(STAGES - 1);
            uint4 q = lds128(sbuf + (k & (STAGES - 1)) * 512);
            size_t row = (size_t)gwarp + (size_t)k * nwarps;
            float e0 = __expf(__uint_as_float(q.x));
            float e1 = __expf(__uint_as_float(q.y));
            float e2 = __expf(__uint_as_float(q.z));
            float e3 = __expf(__uint_as_float(q.w));
            float p = fmaf(e0, va.x, fmaf(e1, va.y, fmaf(e2, va.z, e3 * va.w)));
            #pragma unroll
            for (int o = 16; o; o >>= 1) p += __shfl_xor_sync(0xffffffffu, p, o);
            float u = 1.0f / p;
            float4 o4;
            o4.x = u * e0 * vb.x; o4.y = u * e1 * vb.y;
            o4.z = u * e2 * vb.z; o4.w = u * e3 * vb.w;
            stg_hint_f4(&out4[row * 32 + lane], o4, pol_ef);
            if (j < nrows)
                cp_async16(sbuf + (j & (STAGES - 1)) * 512,
                           S + ((size_t)gwarp + (size_t)j * nwarps) * C + lane * 4);
            CP_COMMIT();
            ++j;
        }
        CP_WAIT(0);
    }
}

// ---------------------------------------------------------------------------
extern "C" void kernel_launch(void* const* d_in, const int* in_sizes, int n_in,
                              void* d_out, int out_size) {
    const float* S        = (const float*)d_in[2];
    const float* ratios   = (const float*)d_in[3];
    const int*   totalnum = (const int*)d_in[5];
    const int N = in_sizes[2] / C;

    init_k<<<1, C>>>(ratios, totalnum);
    grand_k<<<PGRID, PBLK>>>(S, (float*)d_out, N);
}